// round 2
// baseline (speedup 1.0000x reference)
#include <cuda_runtime.h>
#include <math.h>

#define N_NODES 8192
#define H 256
#define NF 256
#define R_MIX 0.3f
#define C_SIM 0.8f
#define LOG2F_ 0.69314718055994530942f
#define MAXM 128
#define ROWSTRIDE 257   // padded row stride in pair-kernel smem (bank-conflict free)

// ---------------- scratch (static device globals; no runtime allocation) ---------
__device__ float g_t [24576 * 256];   // intermediate (reused: scalar then vector)
__device__ float g_si[ 8192 * 256];   // scalar branch output  [N,H]
__device__ float g_vi[24576 * 256];   // vector branch output  [N,3,H] flattened
__device__ int   g_counts [NF];
__device__ int   g_offsets[NF + 1];
__device__ int   g_nodes  [N_NODES];
__device__ float g_svar[NF], g_vvar[NF], g_ssim[NF], g_dir[NF];
__device__ float g_inv_s[N_NODES];
__device__ float g_inv_v[N_NODES * 3];

__device__ __forceinline__ float sspf(float x) {
    // softplus(x) - log(2), numerically stable
    float ax = fabsf(x);
    return fmaxf(x, 0.f) + log1pf(__expf(-ax)) - LOG2F_;
}

// ---------------- fragment bookkeeping ----------------
__global__ void k_zero() {
    g_counts[threadIdx.x] = 0;
}

// fragment_ids arrive as int32 (JAX x64 is disabled by default, so the
// reference's "int64" randint is silently int32). Guard range anyway.
__global__ void k_count(const int* __restrict__ frag) {
    int i = blockIdx.x * 256 + threadIdx.x;
    int f = frag[i];
    if (f >= 0 && f < NF) atomicAdd(&g_counts[f], 1);
}

__global__ void k_scan() {
    __shared__ int s[256];
    int t = threadIdx.x;
    s[t] = g_counts[t];
    __syncthreads();
    for (int d = 1; d < 256; d <<= 1) {
        int v = (t >= d) ? s[t - d] : 0;
        __syncthreads();
        s[t] += v;
        __syncthreads();
    }
    g_offsets[t] = s[t] - g_counts[t];
    if (t == 255) g_offsets[256] = s[255];
}

// Deterministic compaction: block f scans all nodes in order, keeps frag==f.
__global__ void k_build(const int* __restrict__ frag) {
    int f = blockIdx.x;
    __shared__ int wc[8];
    __shared__ int base;
    if (threadIdx.x == 0) base = g_offsets[f];
    __syncthreads();
    int lane = threadIdx.x & 31, w = threadIdx.x >> 5;
    for (int c = 0; c < N_NODES; c += 256) {
        int i = c + threadIdx.x;
        bool m = (frag[i] == f);
        unsigned bal = __ballot_sync(0xffffffffu, m);
        if (lane == 0) wc[w] = __popc(bal);
        __syncthreads();
        int woff = 0;
        for (int k = 0; k < w; k++) woff += wc[k];
        int tot = 0;
        for (int k = 0; k < 8; k++) tot += wc[k];
        if (m) {
            int dst = base + woff + __popc(bal & ((1u << lane) - 1u));
            if (dst >= 0 && dst < N_NODES) g_nodes[dst] = i;
        }
        __syncthreads();
        if (threadIdx.x == 0) base += tot;
        __syncthreads();
    }
}

// ---------------- fp32 SGEMM: C[M,256] = op( mix(A1,A2) @ B + bias ) ----------------
// BM=BN=64, BK=16, 256 threads, 4x4 register tile per thread.
// A2 != null => A = R*A1 + (1-R)*A2 (fused mix). useSSP => shifted-softplus epilogue.
__global__ void k_gemm(const float* __restrict__ A1, const float* __restrict__ A2,
                       const float* __restrict__ B, const float* __restrict__ bias,
                       float* __restrict__ Cc, int useSSP)
{
    __shared__ float As[16][64];
    __shared__ float Bs[16][64];
    int tid = threadIdx.x;
    int colBase = blockIdx.x * 64;
    size_t rowBase = (size_t)blockIdx.y * 64;
    int tx = tid & 15, ty = tid >> 4;
    int ar = tid >> 2, ac = (tid & 3) * 4;   // A loader: row ar, 4 k-cols at ac
    int br = tid >> 4, bc = (tid & 15) * 4;  // B loader: k-row br, 4 cols at bc

    float acc[4][4];
#pragma unroll
    for (int i = 0; i < 4; i++)
#pragma unroll
        for (int j = 0; j < 4; j++) acc[i][j] = 0.f;

    const float* a1p = A1 + (rowBase + ar) * H + ac;
    const float* a2p = A2 ? (A2 + (rowBase + ar) * H + ac) : nullptr;
    const float* bp  = B + (size_t)br * H + colBase + bc;

    for (int k0 = 0; k0 < H; k0 += 16) {
        float4 av = *(const float4*)(a1p + k0);
        if (a2p) {
            float4 a2 = *(const float4*)(a2p + k0);
            av.x = fmaf(av.x, R_MIX, a2.x * (1.f - R_MIX));
            av.y = fmaf(av.y, R_MIX, a2.y * (1.f - R_MIX));
            av.z = fmaf(av.z, R_MIX, a2.z * (1.f - R_MIX));
            av.w = fmaf(av.w, R_MIX, a2.w * (1.f - R_MIX));
        }
        As[ac + 0][ar] = av.x;
        As[ac + 1][ar] = av.y;
        As[ac + 2][ar] = av.z;
        As[ac + 3][ar] = av.w;
        *(float4*)&Bs[br][bc] = *(const float4*)(bp + (size_t)k0 * H);
        __syncthreads();
#pragma unroll
        for (int k = 0; k < 16; k++) {
            float a[4], b[4];
            *(float4*)a = *(const float4*)&As[k][ty * 4];
            *(float4*)b = *(const float4*)&Bs[k][tx * 4];
#pragma unroll
            for (int i = 0; i < 4; i++)
#pragma unroll
                for (int j = 0; j < 4; j++)
                    acc[i][j] = fmaf(a[i], b[j], acc[i][j]);
        }
        __syncthreads();
    }

#pragma unroll
    for (int i = 0; i < 4; i++) {
        size_t row = rowBase + ty * 4 + i;
#pragma unroll
        for (int j = 0; j < 4; j++) {
            int col = colBase + tx * 4 + j;
            float v = acc[i][j];
            if (bias) v += bias[col];
            if (useSSP) v = sspf(v);
            Cc[row * H + col] = v;
        }
    }
}

// ---------------- per-node inverse L2 norms (warp per node) ----------------
__global__ void k_norms() {
    int gw = (blockIdx.x * blockDim.x + threadIdx.x) >> 5;
    int lane = threadIdx.x & 31;
    if (gw >= N_NODES) return;
    const float* p = g_si + (size_t)gw * H;
    float s = 0.f;
    for (int j = lane; j < H; j += 32) { float v = p[j]; s = fmaf(v, v, s); }
    for (int o = 16; o; o >>= 1) s += __shfl_xor_sync(0xffffffffu, s, o);
    if (lane == 0) g_inv_s[gw] = 1.f / fmaxf(sqrtf(s), 1e-12f);
#pragma unroll
    for (int d = 0; d < 3; d++) {
        const float* q = g_vi + ((size_t)gw * 3 + d) * H;
        float t = 0.f;
        for (int j = lane; j < H; j += 32) { float v = q[j]; t = fmaf(v, v, t); }
        for (int o = 16; o; o >>= 1) t += __shfl_xor_sync(0xffffffffu, t, o);
        if (lane == 0) g_inv_v[gw * 3 + d] = 1.f / fmaxf(sqrtf(t), 1e-12f);
    }
}

// ---------------- per-fragment mean + variance (two-pass, block per fragment) -------
__global__ void k_meanvar() {
    __shared__ float mean[1024];   // 256 scalar + 3*256 vector means
    int f = blockIdx.x, t = threadIdx.x;
    int cnt = g_counts[f], off = g_offsets[f];
    float as = 0.f, a0 = 0.f, a1 = 0.f, a2 = 0.f;
    for (int m = 0; m < cnt; m++) {
        int nd = g_nodes[off + m];
        as += g_si[(size_t)nd * H + t];
        const float* v = g_vi + (size_t)nd * 3 * H;
        a0 += v[t]; a1 += v[H + t]; a2 += v[2 * H + t];
    }
    float invn = 1.f / (float)(cnt > 1 ? cnt : 1);
    mean[t] = as * invn; mean[256 + t] = a0 * invn;
    mean[512 + t] = a1 * invn; mean[768 + t] = a2 * invn;
    __syncthreads();
    float sv = 0.f, vv = 0.f;
    for (int m = 0; m < cnt; m++) {
        int nd = g_nodes[off + m];
        float d0 = g_si[(size_t)nd * H + t] - mean[t];
        sv = fmaf(d0, d0, sv);
        const float* v = g_vi + (size_t)nd * 3 * H;
        float d1 = v[t] - mean[256 + t];
        float d2 = v[H + t] - mean[512 + t];
        float d3 = v[2 * H + t] - mean[768 + t];
        vv = fmaf(d1, d1, vv); vv = fmaf(d2, d2, vv); vv = fmaf(d3, d3, vv);
    }
    __shared__ float red[64];
    for (int o = 16; o; o >>= 1) {
        sv += __shfl_xor_sync(0xffffffffu, sv, o);
        vv += __shfl_xor_sync(0xffffffffu, vv, o);
    }
    int w = t >> 5, lane = t & 31;
    if (lane == 0) { red[w] = sv; red[32 + w] = vv; }
    __syncthreads();
    if (t == 0) {
        float a = 0.f, b = 0.f;
        for (int i = 0; i < 8; i++) { a += red[i]; b += red[32 + i]; }
        g_svar[f] = a; g_vvar[f] = b;
    }
}

// ---------------- intra-fragment pair cosine error (block per fragment) ----------
// Only same-fragment pairs survive the mask: the reference's dense 8192x8192
// similarity GEMM collapses to ~500 pairs per fragment. Normalized rows are cached
// in smem with a padded stride (bank-conflict free strided reads).
__global__ void k_pairs() {
    extern __shared__ float rows[];   // MAXM * ROWSTRIDE floats
    int f = blockIdx.x, t = threadIdx.x;
    int cnt = g_counts[f], off = g_offsets[f];
    int w = t >> 5, lane = t & 31;
    float sacc = 0.f, dacc = 0.f;

    if (cnt >= 2 && cnt <= MAXM) {
        for (int feat = 0; feat < 4; feat++) {
            for (int r = 0; r < cnt; r++) {
                int nd = g_nodes[off + r];
                const float* src; float inv;
                if (feat == 0) { src = g_si + (size_t)nd * H; inv = g_inv_s[nd]; }
                else { src = g_vi + ((size_t)nd * 3 + (feat - 1)) * H; inv = g_inv_v[nd * 3 + feat - 1]; }
                rows[r * ROWSTRIDE + t] = src[t] * inv;
            }
            __syncthreads();
            float acc = 0.f;
            for (int a = w; a < cnt - 1; a += 8) {
                const float* ra = rows + a * ROWSTRIDE;
                for (int b = a + 1 + lane; b < cnt; b += 32) {
                    const float* rb = rows + b * ROWSTRIDE;
                    float dot = 0.f;
#pragma unroll 8
                    for (int k = 0; k < H; k++) dot = fmaf(ra[k], rb[k], dot);
                    float e = dot - C_SIM;
                    acc = fmaf(e, e, acc);
                }
            }
            if (feat == 0) sacc = acc; else dacc += acc;
            __syncthreads();
        }
    } else if (cnt > MAXM) {
        // robustness fallback (never expected for this distribution): gmem-direct
        for (int feat = 0; feat < 4; feat++) {
            float acc = 0.f;
            for (int a = w; a < cnt - 1; a += 8) {
                int na = g_nodes[off + a];
                const float* ra; float inva;
                if (feat == 0) { ra = g_si + (size_t)na * H; inva = g_inv_s[na]; }
                else { ra = g_vi + ((size_t)na * 3 + (feat - 1)) * H; inva = g_inv_v[na * 3 + feat - 1]; }
                for (int b = a + 1 + lane; b < cnt; b += 32) {
                    int nb = g_nodes[off + b];
                    const float* rb; float invb;
                    if (feat == 0) { rb = g_si + (size_t)nb * H; invb = g_inv_s[nb]; }
                    else { rb = g_vi + ((size_t)nb * 3 + (feat - 1)) * H; invb = g_inv_v[nb * 3 + feat - 1]; }
                    float dot = 0.f;
                    for (int k = 0; k < H; k++) dot = fmaf(ra[k], rb[k], dot);
                    float e = dot * inva * invb - C_SIM;
                    acc = fmaf(e, e, acc);
                }
            }
            if (feat == 0) sacc = acc; else dacc += acc;
        }
    }

    __shared__ float red[64];
    for (int o = 16; o; o >>= 1) {
        sacc += __shfl_xor_sync(0xffffffffu, sacc, o);
        dacc += __shfl_xor_sync(0xffffffffu, dacc, o);
    }
    if (lane == 0) { red[w] = sacc; red[32 + w] = dacc; }
    __syncthreads();
    if (t == 0) {
        float a = 0.f, b = 0.f;
        for (int i = 0; i < 8; i++) { a += red[i]; b += red[32 + i]; }
        g_ssim[f] = a; g_dir[f] = b;
    }
}

// ---------------- final scalar ----------------
__global__ void k_final(float* __restrict__ out) {
    int f = threadIdx.x;
    float n  = (float)g_counts[f];
    float pc = n * (n - 1.f) * 0.5f;
    float ns  = fmaxf(n, 1.f);
    float pcs = fmaxf(pc, 1.f);
    float sl = g_svar[f] / ns + g_ssim[f] / pcs;
    float vl = g_vvar[f] / ns + g_dir[f] / (3.f * pcs);
    float fl = 0.5f * sl + 0.5f * vl;
    float val  = (pc > 0.f) ? fl : 0.f;
    float cntv = (pc > 0.f) ? 1.f : 0.f;
    __shared__ float red[64];
    for (int o = 16; o; o >>= 1) {
        val  += __shfl_xor_sync(0xffffffffu, val, o);
        cntv += __shfl_xor_sync(0xffffffffu, cntv, o);
    }
    int w = f >> 5, lane = f & 31;
    if (lane == 0) { red[w] = val; red[32 + w] = cntv; }
    __syncthreads();
    if (f == 0) {
        float tot = 0.f, tc = 0.f;
        for (int i = 0; i < 8; i++) { tot += red[i]; tc += red[32 + i]; }
        out[0] = (tc > 0.f) ? tot / fmaxf(tc, 1.f) : 0.f;
    }
}

// ---------------- launch ----------------
extern "C" void kernel_launch(void* const* d_in, const int* in_sizes, int n_in,
                              void* d_out, int out_size)
{
    const float* ss = (const float*)d_in[0];
    const float* sl = (const float*)d_in[1];
    const float* vs = (const float*)d_in[2];
    const float* vl = (const float*)d_in[3];
    const float* W1 = (const float*)d_in[4];
    const float* b1 = (const float*)d_in[5];
    const float* W2 = (const float*)d_in[6];
    const float* b2 = (const float*)d_in[7];
    const float* V1 = (const float*)d_in[8];
    const float* V2 = (const float*)d_in[9];
    const int*   frag = (const int*)d_in[10];   // int32 (JAX x64 disabled)
    float* out = (float*)d_out;

    void *pt, *psi, *pvi;
    cudaGetSymbolAddress(&pt,  g_t);
    cudaGetSymbolAddress(&psi, g_si);
    cudaGetSymbolAddress(&pvi, g_vi);

    k_zero<<<1, 256>>>();
    k_count<<<N_NODES / 256, 256>>>(frag);
    k_scan<<<1, 256>>>();
    k_build<<<NF, 256>>>(frag);

    dim3 gsc(4, 128);   // M=8192
    dim3 gvc(4, 384);   // M=24576
    k_gemm<<<gsc, 256>>>(ss, sl, W1, b1, (float*)pt, 1);
    k_gemm<<<gsc, 256>>>((float*)pt, nullptr, W2, b2, (float*)psi, 0);
    k_gemm<<<gvc, 256>>>(vs, vl, V1, nullptr, (float*)pt, 1);
    k_gemm<<<gvc, 256>>>((float*)pt, nullptr, V2, nullptr, (float*)pvi, 0);

    k_norms<<<N_NODES * 32 / 256, 256>>>();
    k_meanvar<<<NF, 256>>>();

    cudaFuncSetAttribute(k_pairs, cudaFuncAttributeMaxDynamicSharedMemorySize,
                         MAXM * ROWSTRIDE * 4);
    k_pairs<<<NF, 256, MAXM * ROWSTRIDE * 4>>>();

    k_final<<<1, 256>>>(out);
}

// round 3
// speedup vs baseline: 1.0968x; 1.0968x over previous
#include <cuda_runtime.h>
#include <math.h>

#define N_NODES 8192
#define H 256
#define NF 256
#define R_MIX 0.3f
#define C_SIM 0.8f
#define LOG2F_ 0.69314718055994530942f
#define MAXM 128
#define ROWSTRIDE 257   // padded row stride in pair-kernel smem

#define BM 128
#define BN 128
#define BK 16

// ---------------- scratch (static device globals; no runtime allocation) ---------
__device__ float g_t [24576 * 256];   // intermediate (reused: scalar then vector)
__device__ float g_si[ 8192 * 256];   // scalar branch output  [N,H]
__device__ float g_vi[24576 * 256];   // vector branch output  [N,3,H] flattened
__device__ int   g_counts [NF];
__device__ int   g_offsets[NF + 1];
__device__ int   g_nodes  [N_NODES];
__device__ float g_svar[NF], g_vvar[NF], g_ssim[NF], g_dir[NF];
__device__ float g_inv_s[N_NODES];
__device__ float g_inv_v[N_NODES * 3];

__device__ __forceinline__ float sspf(float x) {
    float ax = fabsf(x);
    return fmaxf(x, 0.f) + log1pf(__expf(-ax)) - LOG2F_;
}

// packed f32x2 helpers (SASS FFMA2 — ptxas won't auto-fuse; PTX-only path)
__device__ __forceinline__ unsigned long long dup2(float a) {
    unsigned long long r;
    asm("mov.b64 %0, {%1, %1};" : "=l"(r) : "f"(a));
    return r;
}
__device__ __forceinline__ void fma2(unsigned long long& d, unsigned long long a,
                                     unsigned long long b) {
    asm("fma.rn.f32x2 %0, %1, %2, %0;" : "+l"(d) : "l"(a), "l"(b));
}
__device__ __forceinline__ void unpack2(unsigned long long v, float& lo, float& hi) {
    asm("mov.b64 {%0, %1}, %2;" : "=f"(lo), "=f"(hi) : "l"(v));
}

// ---------------- fragment bookkeeping ----------------
__global__ void k_zero() { g_counts[threadIdx.x] = 0; }

// fragment_ids arrive as int32 (JAX x64 disabled => "int64" randint is int32).
__global__ void k_count(const int* __restrict__ frag) {
    int i = blockIdx.x * 256 + threadIdx.x;
    int f = frag[i];
    if (f >= 0 && f < NF) atomicAdd(&g_counts[f], 1);
}

__global__ void k_scan() {
    __shared__ int s[256];
    int t = threadIdx.x;
    s[t] = g_counts[t];
    __syncthreads();
    for (int d = 1; d < 256; d <<= 1) {
        int v = (t >= d) ? s[t - d] : 0;
        __syncthreads();
        s[t] += v;
        __syncthreads();
    }
    g_offsets[t] = s[t] - g_counts[t];
    if (t == 255) g_offsets[256] = s[255];
}

// Deterministic compaction: block f scans all nodes in index order, keeps frag==f.
__global__ void k_build(const int* __restrict__ frag) {
    int f = blockIdx.x;
    __shared__ int wc[8];
    __shared__ int base;
    if (threadIdx.x == 0) base = g_offsets[f];
    __syncthreads();
    int lane = threadIdx.x & 31, w = threadIdx.x >> 5;
    for (int c = 0; c < N_NODES; c += 256) {
        int i = c + threadIdx.x;
        bool m = (frag[i] == f);
        unsigned bal = __ballot_sync(0xffffffffu, m);
        if (lane == 0) wc[w] = __popc(bal);
        __syncthreads();
        int woff = 0;
        for (int k = 0; k < w; k++) woff += wc[k];
        int tot = 0;
        for (int k = 0; k < 8; k++) tot += wc[k];
        if (m) {
            int dst = base + woff + __popc(bal & ((1u << lane) - 1u));
            if (dst >= 0 && dst < N_NODES) g_nodes[dst] = i;
        }
        __syncthreads();
        if (threadIdx.x == 0) base += tot;
        __syncthreads();
    }
}

// ------------- fp32 SGEMM: C[M,256] = op( mix(A1,A2) @ B + bias ) ---------------
// 128x128x16 block tile, 256 threads, 8x8 per-thread micro-tile computed as
// packed f32x2 (FFMA2): 32 packed FMA + 4 LDS.128 per k-step per thread.
// Double-buffered smem, one __syncthreads per K-tile.
__device__ __forceinline__ void gloadA(const float* __restrict__ a1p,
                                       const float* __restrict__ a2p,
                                       int k0, float4& x, float4& y) {
    x = *(const float4*)(a1p + k0);
    y = *(const float4*)(a1p + k0 + 4);
    if (a2p) {
        float4 u = *(const float4*)(a2p + k0);
        float4 v = *(const float4*)(a2p + k0 + 4);
        const float w = 1.f - R_MIX;
        x.x = fmaf(x.x, R_MIX, u.x * w); x.y = fmaf(x.y, R_MIX, u.y * w);
        x.z = fmaf(x.z, R_MIX, u.z * w); x.w = fmaf(x.w, R_MIX, u.w * w);
        y.x = fmaf(y.x, R_MIX, v.x * w); y.y = fmaf(y.y, R_MIX, v.y * w);
        y.z = fmaf(y.z, R_MIX, v.z * w); y.w = fmaf(y.w, R_MIX, v.w * w);
    }
}

__global__ __launch_bounds__(256, 2)
void k_gemm(const float* __restrict__ A1, const float* __restrict__ A2,
            const float* __restrict__ B, const float* __restrict__ bias,
            float* __restrict__ Cc, int useSSP)
{
    __shared__ float As[2][BK][BM];
    __shared__ float Bs[2][BK][BN];
    const int tid = threadIdx.x;
    const int tx = tid & 15;          // col group 0..15
    const int ty = tid >> 4;          // row group 0..15
    const size_t rowBase = (size_t)blockIdx.y * BM;
    const int colBase = blockIdx.x * BN;

    // loaders: A thread -> row arow, k-cols acol..acol+7 (consecutive-lane rows
    // make the transposed smem stores conflict-free). B thread -> k-row brow,
    // cols bcol..bcol+7 (coalesced).
    const int arow = tid & 127;
    const int acol = (tid >> 7) * 8;
    const int brow = tid >> 4;
    const int bcol = (tid & 15) * 8;

    const float* a1p = A1 + (rowBase + arow) * H + acol;
    const float* a2p = A2 ? A2 + (rowBase + arow) * H + acol : nullptr;
    const float* bp  = B + (size_t)brow * H + colBase + bcol;

    unsigned long long acc[8][4];
#pragma unroll
    for (int r = 0; r < 8; r++)
#pragma unroll
        for (int c = 0; c < 4; c++) acc[r][c] = 0ull;

    float4 ax, ay, bx, by;
    // prologue: tile 0
    gloadA(a1p, a2p, 0, ax, ay);
    bx = *(const float4*)(bp);
    by = *(const float4*)(bp + 4);
    {
        float* as = &As[0][0][0];
        as[(acol + 0) * BM + arow] = ax.x; as[(acol + 1) * BM + arow] = ax.y;
        as[(acol + 2) * BM + arow] = ax.z; as[(acol + 3) * BM + arow] = ax.w;
        as[(acol + 4) * BM + arow] = ay.x; as[(acol + 5) * BM + arow] = ay.y;
        as[(acol + 6) * BM + arow] = ay.z; as[(acol + 7) * BM + arow] = ay.w;
        *(float4*)&Bs[0][brow][bcol] = bx;
        *(float4*)&Bs[0][brow][bcol + 4] = by;
    }
    __syncthreads();

    const int NT = H / BK;   // 16
    for (int t = 0; t < NT; t++) {
        int cur = t & 1;
        if (t + 1 < NT) {
            int k0 = (t + 1) * BK;
            gloadA(a1p, a2p, k0, ax, ay);
            bx = *(const float4*)(bp + (size_t)k0 * H);
            by = *(const float4*)(bp + (size_t)k0 * H + 4);
        }
        const float* as = &As[cur][0][0];
        const float* bs = &Bs[cur][0][0];
#pragma unroll
        for (int k = 0; k < BK; k++) {
            float4 av0 = *(const float4*)(as + k * BM + ty * 4);
            float4 av1 = *(const float4*)(as + k * BM + 64 + ty * 4);
            ulonglong2 bq0 = *(const ulonglong2*)(bs + k * BN + tx * 4);
            ulonglong2 bq1 = *(const ulonglong2*)(bs + k * BN + 64 + tx * 4);
            float a8[8] = {av0.x, av0.y, av0.z, av0.w, av1.x, av1.y, av1.z, av1.w};
#pragma unroll
            for (int r = 0; r < 8; r++) {
                unsigned long long ad = dup2(a8[r]);
                fma2(acc[r][0], ad, bq0.x);
                fma2(acc[r][1], ad, bq0.y);
                fma2(acc[r][2], ad, bq1.x);
                fma2(acc[r][3], ad, bq1.y);
            }
        }
        if (t + 1 < NT) {
            int nxt = (t + 1) & 1;
            float* asw = &As[nxt][0][0];
            asw[(acol + 0) * BM + arow] = ax.x; asw[(acol + 1) * BM + arow] = ax.y;
            asw[(acol + 2) * BM + arow] = ax.z; asw[(acol + 3) * BM + arow] = ax.w;
            asw[(acol + 4) * BM + arow] = ay.x; asw[(acol + 5) * BM + arow] = ay.y;
            asw[(acol + 6) * BM + arow] = ay.z; asw[(acol + 7) * BM + arow] = ay.w;
            *(float4*)&Bs[nxt][brow][bcol] = bx;
            *(float4*)&Bs[nxt][brow][bcol + 4] = by;
            __syncthreads();
        }
    }

    // epilogue
    float4 bb[2];
    if (bias) {
        bb[0] = *(const float4*)&bias[colBase + tx * 4];
        bb[1] = *(const float4*)&bias[colBase + 64 + tx * 4];
    }
#pragma unroll
    for (int r = 0; r < 8; r++) {
        size_t row = rowBase + ((r < 4) ? (ty * 4 + r) : (64 + ty * 4 + r - 4));
#pragma unroll
        for (int q = 0; q < 2; q++) {
            int col = colBase + q * 64 + tx * 4;
            float v0, v1, v2, v3;
            unpack2(acc[r][q * 2 + 0], v0, v1);
            unpack2(acc[r][q * 2 + 1], v2, v3);
            if (bias) { v0 += bb[q].x; v1 += bb[q].y; v2 += bb[q].z; v3 += bb[q].w; }
            if (useSSP) { v0 = sspf(v0); v1 = sspf(v1); v2 = sspf(v2); v3 = sspf(v3); }
            float4 o; o.x = v0; o.y = v1; o.z = v2; o.w = v3;
            *(float4*)&Cc[row * H + col] = o;
        }
    }
}

// ---------------- per-node inverse L2 norms (warp per node) ----------------
__global__ void k_norms() {
    int gw = (blockIdx.x * blockDim.x + threadIdx.x) >> 5;
    int lane = threadIdx.x & 31;
    if (gw >= N_NODES) return;
    const float* p = g_si + (size_t)gw * H;
    float s = 0.f;
    for (int j = lane; j < H; j += 32) { float v = p[j]; s = fmaf(v, v, s); }
    for (int o = 16; o; o >>= 1) s += __shfl_xor_sync(0xffffffffu, s, o);
    if (lane == 0) g_inv_s[gw] = 1.f / fmaxf(sqrtf(s), 1e-12f);
#pragma unroll
    for (int d = 0; d < 3; d++) {
        const float* q = g_vi + ((size_t)gw * 3 + d) * H;
        float t = 0.f;
        for (int j = lane; j < H; j += 32) { float v = q[j]; t = fmaf(v, v, t); }
        for (int o = 16; o; o >>= 1) t += __shfl_xor_sync(0xffffffffu, t, o);
        if (lane == 0) g_inv_v[gw * 3 + d] = 1.f / fmaxf(sqrtf(t), 1e-12f);
    }
}

// ---------------- per-fragment mean + variance (two-pass, block per fragment) -------
__global__ void k_meanvar() {
    __shared__ float mean[1024];
    int f = blockIdx.x, t = threadIdx.x;
    int cnt = g_counts[f], off = g_offsets[f];
    float as = 0.f, a0 = 0.f, a1 = 0.f, a2 = 0.f;
    for (int m = 0; m < cnt; m++) {
        int nd = g_nodes[off + m];
        as += g_si[(size_t)nd * H + t];
        const float* v = g_vi + (size_t)nd * 3 * H;
        a0 += v[t]; a1 += v[H + t]; a2 += v[2 * H + t];
    }
    float invn = 1.f / (float)(cnt > 1 ? cnt : 1);
    mean[t] = as * invn; mean[256 + t] = a0 * invn;
    mean[512 + t] = a1 * invn; mean[768 + t] = a2 * invn;
    __syncthreads();
    float sv = 0.f, vv = 0.f;
    for (int m = 0; m < cnt; m++) {
        int nd = g_nodes[off + m];
        float d0 = g_si[(size_t)nd * H + t] - mean[t];
        sv = fmaf(d0, d0, sv);
        const float* v = g_vi + (size_t)nd * 3 * H;
        float d1 = v[t] - mean[256 + t];
        float d2 = v[H + t] - mean[512 + t];
        float d3 = v[2 * H + t] - mean[768 + t];
        vv = fmaf(d1, d1, vv); vv = fmaf(d2, d2, vv); vv = fmaf(d3, d3, vv);
    }
    __shared__ float red[64];
    for (int o = 16; o; o >>= 1) {
        sv += __shfl_xor_sync(0xffffffffu, sv, o);
        vv += __shfl_xor_sync(0xffffffffu, vv, o);
    }
    int w = t >> 5, lane = t & 31;
    if (lane == 0) { red[w] = sv; red[32 + w] = vv; }
    __syncthreads();
    if (t == 0) {
        float a = 0.f, b = 0.f;
        for (int i = 0; i < 8; i++) { a += red[i]; b += red[32 + i]; }
        g_svar[f] = a; g_vvar[f] = b;
    }
}

// ---------------- intra-fragment pair cosine error (block per fragment) ----------
__global__ void k_pairs() {
    extern __shared__ float rows[];   // MAXM * ROWSTRIDE floats
    int f = blockIdx.x, t = threadIdx.x;
    int cnt = g_counts[f], off = g_offsets[f];
    int w = t >> 5, lane = t & 31;
    float sacc = 0.f, dacc = 0.f;

    if (cnt >= 2 && cnt <= MAXM) {
        for (int feat = 0; feat < 4; feat++) {
            for (int r = 0; r < cnt; r++) {
                int nd = g_nodes[off + r];
                const float* src; float inv;
                if (feat == 0) { src = g_si + (size_t)nd * H; inv = g_inv_s[nd]; }
                else { src = g_vi + ((size_t)nd * 3 + (feat - 1)) * H; inv = g_inv_v[nd * 3 + feat - 1]; }
                rows[r * ROWSTRIDE + t] = src[t] * inv;
            }
            __syncthreads();
            float acc = 0.f;
            for (int a = w; a < cnt - 1; a += 8) {
                const float* ra = rows + a * ROWSTRIDE;
                for (int b = a + 1 + lane; b < cnt; b += 32) {
                    const float* rb = rows + b * ROWSTRIDE;
                    float dot = 0.f;
#pragma unroll 8
                    for (int k = 0; k < H; k++) dot = fmaf(ra[k], rb[k], dot);
                    float e = dot - C_SIM;
                    acc = fmaf(e, e, acc);
                }
            }
            if (feat == 0) sacc = acc; else dacc += acc;
            __syncthreads();
        }
    } else if (cnt > MAXM) {
        for (int feat = 0; feat < 4; feat++) {
            float acc = 0.f;
            for (int a = w; a < cnt - 1; a += 8) {
                int na = g_nodes[off + a];
                const float* ra; float inva;
                if (feat == 0) { ra = g_si + (size_t)na * H; inva = g_inv_s[na]; }
                else { ra = g_vi + ((size_t)na * 3 + (feat - 1)) * H; inva = g_inv_v[na * 3 + feat - 1]; }
                for (int b = a + 1 + lane; b < cnt; b += 32) {
                    int nb = g_nodes[off + b];
                    const float* rb; float invb;
                    if (feat == 0) { rb = g_si + (size_t)nb * H; invb = g_inv_s[nb]; }
                    else { rb = g_vi + ((size_t)nb * 3 + (feat - 1)) * H; invb = g_inv_v[nb * 3 + feat - 1]; }
                    float dot = 0.f;
                    for (int k = 0; k < H; k++) dot = fmaf(ra[k], rb[k], dot);
                    float e = dot * inva * invb - C_SIM;
                    acc = fmaf(e, e, acc);
                }
            }
            if (feat == 0) sacc = acc; else dacc += acc;
        }
    }

    __shared__ float red[64];
    for (int o = 16; o; o >>= 1) {
        sacc += __shfl_xor_sync(0xffffffffu, sacc, o);
        dacc += __shfl_xor_sync(0xffffffffu, dacc, o);
    }
    if (lane == 0) { red[w] = sacc; red[32 + w] = dacc; }
    __syncthreads();
    if (t == 0) {
        float a = 0.f, b = 0.f;
        for (int i = 0; i < 8; i++) { a += red[i]; b += red[32 + i]; }
        g_ssim[f] = a; g_dir[f] = b;
    }
}

// ---------------- final scalar ----------------
__global__ void k_final(float* __restrict__ out) {
    int f = threadIdx.x;
    float n  = (float)g_counts[f];
    float pc = n * (n - 1.f) * 0.5f;
    float ns  = fmaxf(n, 1.f);
    float pcs = fmaxf(pc, 1.f);
    float sl = g_svar[f] / ns + g_ssim[f] / pcs;
    float vl = g_vvar[f] / ns + g_dir[f] / (3.f * pcs);
    float fl = 0.5f * sl + 0.5f * vl;
    float val  = (pc > 0.f) ? fl : 0.f;
    float cntv = (pc > 0.f) ? 1.f : 0.f;
    __shared__ float red[64];
    for (int o = 16; o; o >>= 1) {
        val  += __shfl_xor_sync(0xffffffffu, val, o);
        cntv += __shfl_xor_sync(0xffffffffu, cntv, o);
    }
    int w = f >> 5, lane = f & 31;
    if (lane == 0) { red[w] = val; red[32 + w] = cntv; }
    __syncthreads();
    if (f == 0) {
        float tot = 0.f, tc = 0.f;
        for (int i = 0; i < 8; i++) { tot += red[i]; tc += red[32 + i]; }
        out[0] = (tc > 0.f) ? tot / fmaxf(tc, 1.f) : 0.f;
    }
}

// ---------------- launch ----------------
extern "C" void kernel_launch(void* const* d_in, const int* in_sizes, int n_in,
                              void* d_out, int out_size)
{
    const float* ss = (const float*)d_in[0];
    const float* sl = (const float*)d_in[1];
    const float* vs = (const float*)d_in[2];
    const float* vl = (const float*)d_in[3];
    const float* W1 = (const float*)d_in[4];
    const float* b1 = (const float*)d_in[5];
    const float* W2 = (const float*)d_in[6];
    const float* b2 = (const float*)d_in[7];
    const float* V1 = (const float*)d_in[8];
    const float* V2 = (const float*)d_in[9];
    const int*   frag = (const int*)d_in[10];
    float* out = (float*)d_out;

    void *pt, *psi, *pvi;
    cudaGetSymbolAddress(&pt,  g_t);
    cudaGetSymbolAddress(&psi, g_si);
    cudaGetSymbolAddress(&pvi, g_vi);

    k_zero<<<1, 256>>>();
    k_count<<<N_NODES / 256, 256>>>(frag);
    k_scan<<<1, 256>>>();
    k_build<<<NF, 256>>>(frag);

    dim3 gsc(2, 64);    // M=8192  / 128
    dim3 gvc(2, 192);   // M=24576 / 128
    k_gemm<<<gsc, 256>>>(ss, sl, W1, b1, (float*)pt, 1);
    k_gemm<<<gsc, 256>>>((float*)pt, nullptr, W2, b2, (float*)psi, 0);
    k_gemm<<<gvc, 256>>>(vs, vl, V1, nullptr, (float*)pt, 1);
    k_gemm<<<gvc, 256>>>((float*)pt, nullptr, V2, nullptr, (float*)pvi, 0);

    k_norms<<<N_NODES * 32 / 256, 256>>>();
    k_meanvar<<<NF, 256>>>();

    cudaFuncSetAttribute(k_pairs, cudaFuncAttributeMaxDynamicSharedMemorySize,
                         MAXM * ROWSTRIDE * 4);
    k_pairs<<<NF, 256, MAXM * ROWSTRIDE * 4>>>();

    k_final<<<1, 256>>>(out);
}

// round 4
// speedup vs baseline: 1.7373x; 1.5840x over previous
#include <cuda_runtime.h>
#include <cuda_bf16.h>
#include <math.h>
#include <stdint.h>

#define N_NODES 8192
#define H 256
#define NF 256
#define R_MIX 0.3f
#define C_SIM 0.8f
#define LOG2F_ 0.69314718055994530942f
#define MAXM 128
#define ROWSTRIDE 260   // pair-kernel smem row stride (float4-aligned, conflict-free)

// ---------------- scratch (static device globals) ----------------
__device__ float g_t [24576 * 256];
__device__ float g_si[ 8192 * 256];
__device__ float g_vi[24576 * 256];
__device__ int   g_chunk[256 * 256];   // [chunk][frag] counts -> local prefixes
__device__ int   g_counts [NF];
__device__ int   g_offsets[NF + 1];
__device__ int   g_nodes  [N_NODES];
__device__ float g_svar[NF], g_vvar[NF], g_ssim[NF], g_dir[NF];
__device__ float g_inv_s[N_NODES];
__device__ float g_inv_v[N_NODES * 3];

__device__ __forceinline__ float sspf(float x) {
    float ax = fabsf(x);
    return fmaxf(x, 0.f) + log1pf(__expf(-ax)) - LOG2F_;
}

// ---------------- bf16 split helpers ----------------
__device__ __forceinline__ uint32_t pk2(float a, float b) {
    __nv_bfloat162 t = __floats2bfloat162_rn(a, b);
    return *reinterpret_cast<uint32_t*>(&t);
}
__device__ __forceinline__ float bres(float x) {
    __nv_bfloat16 h = __float2bfloat16(x);
    return x - __bfloat162float(h);
}

// ---------------- mma/ldmatrix wrappers ----------------
__device__ __forceinline__ void ldsm4(uint32_t addr, uint32_t* r) {
    asm volatile("ldmatrix.sync.aligned.m8n8.x4.shared.b16 {%0,%1,%2,%3}, [%4];"
                 : "=r"(r[0]), "=r"(r[1]), "=r"(r[2]), "=r"(r[3]) : "r"(addr));
}
__device__ __forceinline__ void ldsm4t(uint32_t addr, uint32_t* r) {
    asm volatile("ldmatrix.sync.aligned.m8n8.x4.trans.shared.b16 {%0,%1,%2,%3}, [%4];"
                 : "=r"(r[0]), "=r"(r[1]), "=r"(r[2]), "=r"(r[3]) : "r"(addr));
}
__device__ __forceinline__ void mma16816(float* c, const uint32_t* a, uint32_t b0, uint32_t b1) {
    asm volatile(
        "mma.sync.aligned.m16n8k16.row.col.f32.bf16.bf16.f32 "
        "{%0,%1,%2,%3},{%4,%5,%6,%7},{%8,%9},{%0,%1,%2,%3};"
        : "+f"(c[0]), "+f"(c[1]), "+f"(c[2]), "+f"(c[3])
        : "r"(a[0]), "r"(a[1]), "r"(a[2]), "r"(a[3]), "r"(b0), "r"(b1));
}

// ---------------- fragment bookkeeping (deterministic counting sort) -----------
// chunk = 32 consecutive nodes handled by one warp.
__global__ void k_hist(const int* __restrict__ frag) {
    int chunk = blockIdx.x * 8 + (threadIdx.x >> 5);
    int lane = threadIdx.x & 31;
    int i = chunk * 32 + lane;
    int f = frag[i];
    unsigned mask = __match_any_sync(0xffffffffu, f);
    int lr = __popc(mask & ((1u << lane) - 1u));
    if (lr == 0 && f >= 0 && f < NF) g_chunk[chunk * 256 + f] = __popc(mask);
}

__global__ void k_scan2() {
    int t = threadIdx.x;  // fragment id
    int running = 0;
    for (int c = 0; c < 256; c++) {
        int idx = c * 256 + t;
        int v = g_chunk[idx];
        g_chunk[idx] = running;   // local prefix within fragment
        running += v;
    }
    g_counts[t] = running;
    __shared__ int s[256];
    s[t] = running;
    __syncthreads();
    for (int d = 1; d < 256; d <<= 1) {
        int v = (t >= d) ? s[t - d] : 0;
        __syncthreads();
        s[t] += v;
        __syncthreads();
    }
    g_offsets[t] = s[t] - running;
    if (t == 255) g_offsets[256] = s[255];
}

__global__ void k_scatter(const int* __restrict__ frag) {
    int chunk = blockIdx.x * 8 + (threadIdx.x >> 5);
    int lane = threadIdx.x & 31;
    int i = chunk * 32 + lane;
    int f = frag[i];
    unsigned mask = __match_any_sync(0xffffffffu, f);
    int lr = __popc(mask & ((1u << lane) - 1u));
    if (f >= 0 && f < NF) {
        int pos = g_offsets[f] + g_chunk[chunk * 256 + f] + lr;
        if (pos >= 0 && pos < N_NODES) g_nodes[pos] = i;
    }
}

// ------------- tensor-core GEMM: C[M,256] = op( mix(A1,A2) @ B + bias ) -----------
// bf16 2-term split (Ah,Al / Bh,Bl), D = Ah*Bh + Al*Bh + Ah*Bl (err ~1.5e-5 rel).
// CTA tile 128x128, 8 warps (2x4) of 64x32, K chunks of 16, double-buffered smem.
// A smem row stride 24 hw (48B), B smem row stride 136 hw (272B): conflict-free ldmatrix.

#define AROW 24
#define BROW 136
#define A_HL (128 * AROW)          // halfwords per (buf,hilo) A plane
#define B_HL (16 * BROW)

__device__ __forceinline__ void gloadA(const float* __restrict__ a1p,
                                       const float* __restrict__ a2p,
                                       int k0, float4& x, float4& y) {
    x = *(const float4*)(a1p + k0);
    y = *(const float4*)(a1p + k0 + 4);
    if (a2p) {
        float4 u = *(const float4*)(a2p + k0);
        float4 v = *(const float4*)(a2p + k0 + 4);
        const float w = 1.f - R_MIX;
        x.x = fmaf(x.x, R_MIX, u.x * w); x.y = fmaf(x.y, R_MIX, u.y * w);
        x.z = fmaf(x.z, R_MIX, u.z * w); x.w = fmaf(x.w, R_MIX, u.w * w);
        y.x = fmaf(y.x, R_MIX, v.x * w); y.y = fmaf(y.y, R_MIX, v.y * w);
        y.z = fmaf(y.z, R_MIX, v.z * w); y.w = fmaf(y.w, R_MIX, v.w * w);
    }
}

__device__ __forceinline__ void cvt_store8(uint16_t* hi_p, uint16_t* lo_p,
                                           const float4& x, const float4& y) {
    uint4 hv, lv;
    hv.x = pk2(x.x, x.y); hv.y = pk2(x.z, x.w);
    hv.z = pk2(y.x, y.y); hv.w = pk2(y.z, y.w);
    lv.x = pk2(bres(x.x), bres(x.y)); lv.y = pk2(bres(x.z), bres(x.w));
    lv.z = pk2(bres(y.x), bres(y.y)); lv.w = pk2(bres(y.z), bres(y.w));
    *reinterpret_cast<uint4*>(hi_p) = hv;
    *reinterpret_cast<uint4*>(lo_p) = lv;
}

__global__ __launch_bounds__(256, 2)
void k_gemm(const float* __restrict__ A1, const float* __restrict__ A2,
            const float* __restrict__ B, const float* __restrict__ bias,
            float* __restrict__ Cc, int useSSP)
{
    // [buf][hilo] planes
    __shared__ __align__(16) uint16_t sA[2][2][A_HL];
    __shared__ __align__(16) uint16_t sB[2][2][B_HL];

    const int tid = threadIdx.x;
    const int lane = tid & 31;
    const int wid = tid >> 5;
    const int warp_m = wid >> 2;       // 0..1
    const int warp_n = wid & 3;        // 0..3
    const size_t rowBase = (size_t)blockIdx.y * 128;
    const int colBase = blockIdx.x * 128;

    // loaders
    const int am = tid >> 1;                 // 0..127
    const int ak = (tid & 1) * 8;            // 0 or 8
    const int bk = tid >> 4;                 // 0..15
    const int bn = (tid & 15) * 8;           // 0..120

    const float* a1p = A1 + (rowBase + am) * H + ak;
    const float* a2p = A2 ? A2 + (rowBase + am) * H + ak : nullptr;
    const float* bp  = B + (size_t)bk * H + colBase + bn;

    // ldmatrix lane base offsets (bytes)
    const int a_row0 = warp_m * 64 + (lane & 7) + ((lane >> 3) & 1) * 8;
    const int a_kgrp = lane >> 4;            // 0/1 -> k+8
    uint32_t aBase = (uint32_t)__cvta_generic_to_shared(&sA[0][0][0])
                   + (uint32_t)((a_row0 * AROW + a_kgrp * 8) * 2);
    const int b_krow = (lane & 7) + ((lane >> 3) & 1) * 8;
    const int b_ngrp = lane >> 4;            // 0/1 -> n+8
    uint32_t bBase = (uint32_t)__cvta_generic_to_shared(&sB[0][0][0])
                   + (uint32_t)((b_krow * BROW + warp_n * 32 + b_ngrp * 8) * 2);

    float acc[4][4][4];
#pragma unroll
    for (int i = 0; i < 4; i++)
#pragma unroll
        for (int j = 0; j < 4; j++)
#pragma unroll
            for (int q = 0; q < 4; q++) acc[i][j][q] = 0.f;

    // prologue: load chunk 0, convert, store
    float4 ax, ay, bx, by;
    gloadA(a1p, a2p, 0, ax, ay);
    bx = *(const float4*)(bp);
    by = *(const float4*)(bp + 4);
    cvt_store8(&sA[0][0][am * AROW + ak], &sA[0][1][am * AROW + ak], ax, ay);
    cvt_store8(&sB[0][0][bk * BROW + bn], &sB[0][1][bk * BROW + bn], bx, by);
    __syncthreads();

    const int NT = H / 16;  // 16
    for (int t = 0; t < NT; t++) {
        if (t + 1 < NT) {
            int k0 = (t + 1) * 16;
            gloadA(a1p, a2p, k0, ax, ay);
            bx = *(const float4*)(bp + (size_t)k0 * H);
            by = *(const float4*)(bp + (size_t)k0 * H + 4);
        }
        int buf = t & 1;
        uint32_t aOff = aBase + (uint32_t)(buf * 2 * A_HL * 2);
        uint32_t bOff = bBase + (uint32_t)(buf * 2 * B_HL * 2);

        uint32_t ah[4][4], bh[2][4], tmp[2][4], al4[4];
#pragma unroll
        for (int mt = 0; mt < 4; mt++) ldsm4(aOff + mt * (16 * AROW * 2), ah[mt]);
#pragma unroll
        for (int st = 0; st < 2; st++) ldsm4t(bOff + st * 32, bh[st]);
        // Ah * Bh
#pragma unroll
        for (int mt = 0; mt < 4; mt++)
#pragma unroll
            for (int nt = 0; nt < 4; nt++)
                mma16816(acc[mt][nt], ah[mt], bh[nt >> 1][(nt & 1) * 2],
                         bh[nt >> 1][(nt & 1) * 2 + 1]);
        // Ah * Bl
#pragma unroll
        for (int st = 0; st < 2; st++) ldsm4t(bOff + B_HL * 2 + st * 32, tmp[st]);
#pragma unroll
        for (int mt = 0; mt < 4; mt++)
#pragma unroll
            for (int nt = 0; nt < 4; nt++)
                mma16816(acc[mt][nt], ah[mt], tmp[nt >> 1][(nt & 1) * 2],
                         tmp[nt >> 1][(nt & 1) * 2 + 1]);
        // Al * Bh
#pragma unroll
        for (int mt = 0; mt < 4; mt++) {
            ldsm4(aOff + A_HL * 2 + mt * (16 * AROW * 2), al4);
#pragma unroll
            for (int nt = 0; nt < 4; nt++)
                mma16816(acc[mt][nt], al4, bh[nt >> 1][(nt & 1) * 2],
                         bh[nt >> 1][(nt & 1) * 2 + 1]);
        }

        if (t + 1 < NT) {
            int nb = (t + 1) & 1;
            cvt_store8(&sA[nb][0][am * AROW + ak], &sA[nb][1][am * AROW + ak], ax, ay);
            cvt_store8(&sB[nb][0][bk * BROW + bn], &sB[nb][1][bk * BROW + bn], bx, by);
        }
        __syncthreads();
    }

    // epilogue: fragment layout stores (quad-of-lanes covers one 32B sector)
#pragma unroll
    for (int mt = 0; mt < 4; mt++) {
        size_t r0 = rowBase + warp_m * 64 + mt * 16 + (lane >> 2);
#pragma unroll
        for (int nt = 0; nt < 4; nt++) {
            int col = colBase + warp_n * 32 + nt * 8 + (lane & 3) * 2;
            float v0 = acc[mt][nt][0], v1 = acc[mt][nt][1];
            float v2 = acc[mt][nt][2], v3 = acc[mt][nt][3];
            if (bias) {
                float2 bb = *(const float2*)&bias[col];
                v0 += bb.x; v1 += bb.y; v2 += bb.x; v3 += bb.y;
            }
            if (useSSP) { v0 = sspf(v0); v1 = sspf(v1); v2 = sspf(v2); v3 = sspf(v3); }
            float2 o0; o0.x = v0; o0.y = v1;
            float2 o1; o1.x = v2; o1.y = v3;
            *(float2*)&Cc[r0 * H + col] = o0;
            *(float2*)&Cc[(r0 + 8) * H + col] = o1;
        }
    }
}

// ---------------- per-node inverse L2 norms (warp per node) ----------------
__global__ void k_norms() {
    int gw = (blockIdx.x * blockDim.x + threadIdx.x) >> 5;
    int lane = threadIdx.x & 31;
    if (gw >= N_NODES) return;
    const float* p = g_si + (size_t)gw * H;
    float s = 0.f;
    for (int j = lane; j < H; j += 32) { float v = p[j]; s = fmaf(v, v, s); }
    for (int o = 16; o; o >>= 1) s += __shfl_xor_sync(0xffffffffu, s, o);
    if (lane == 0) g_inv_s[gw] = 1.f / fmaxf(sqrtf(s), 1e-12f);
#pragma unroll
    for (int d = 0; d < 3; d++) {
        const float* q = g_vi + ((size_t)gw * 3 + d) * H;
        float t = 0.f;
        for (int j = lane; j < H; j += 32) { float v = q[j]; t = fmaf(v, v, t); }
        for (int o = 16; o; o >>= 1) t += __shfl_xor_sync(0xffffffffu, t, o);
        if (lane == 0) g_inv_v[gw * 3 + d] = 1.f / fmaxf(sqrtf(t), 1e-12f);
    }
}

// ---------------- per-fragment mean + variance ----------------
__global__ void k_meanvar() {
    __shared__ float mean[1024];
    int f = blockIdx.x, t = threadIdx.x;
    int cnt = g_counts[f], off = g_offsets[f];
    float as = 0.f, a0 = 0.f, a1 = 0.f, a2 = 0.f;
    for (int m = 0; m < cnt; m++) {
        int nd = g_nodes[off + m];
        as += g_si[(size_t)nd * H + t];
        const float* v = g_vi + (size_t)nd * 3 * H;
        a0 += v[t]; a1 += v[H + t]; a2 += v[2 * H + t];
    }
    float invn = 1.f / (float)(cnt > 1 ? cnt : 1);
    mean[t] = as * invn; mean[256 + t] = a0 * invn;
    mean[512 + t] = a1 * invn; mean[768 + t] = a2 * invn;
    __syncthreads();
    float sv = 0.f, vv = 0.f;
    for (int m = 0; m < cnt; m++) {
        int nd = g_nodes[off + m];
        float d0 = g_si[(size_t)nd * H + t] - mean[t];
        sv = fmaf(d0, d0, sv);
        const float* v = g_vi + (size_t)nd * 3 * H;
        float d1 = v[t] - mean[256 + t];
        float d2 = v[H + t] - mean[512 + t];
        float d3 = v[2 * H + t] - mean[768 + t];
        vv = fmaf(d1, d1, vv); vv = fmaf(d2, d2, vv); vv = fmaf(d3, d3, vv);
    }
    __shared__ float red[64];
    for (int o = 16; o; o >>= 1) {
        sv += __shfl_xor_sync(0xffffffffu, sv, o);
        vv += __shfl_xor_sync(0xffffffffu, vv, o);
    }
    int w = t >> 5, lane = t & 31;
    if (lane == 0) { red[w] = sv; red[32 + w] = vv; }
    __syncthreads();
    if (t == 0) {
        float a = 0.f, b = 0.f;
        for (int i = 0; i < 8; i++) { a += red[i]; b += red[32 + i]; }
        g_svar[f] = a; g_vvar[f] = b;
    }
}

// ---------------- intra-fragment pair cosine error ----------------
__global__ void k_pairs() {
    extern __shared__ float rows[];   // MAXM * ROWSTRIDE floats
    int f = blockIdx.x, t = threadIdx.x;
    int cnt = g_counts[f], off = g_offsets[f];
    int w = t >> 5, lane = t & 31;
    float sacc = 0.f, dacc = 0.f;

    if (cnt >= 2 && cnt <= MAXM) {
        for (int feat = 0; feat < 4; feat++) {
            for (int r = 0; r < cnt; r++) {
                int nd = g_nodes[off + r];
                const float* src; float inv;
                if (feat == 0) { src = g_si + (size_t)nd * H; inv = g_inv_s[nd]; }
                else { src = g_vi + ((size_t)nd * 3 + (feat - 1)) * H; inv = g_inv_v[nd * 3 + feat - 1]; }
                rows[r * ROWSTRIDE + t] = src[t] * inv;
            }
            __syncthreads();
            float acc = 0.f;
            for (int a = w; a < cnt - 1; a += 8) {
                const float4* ra = (const float4*)(rows + a * ROWSTRIDE);
                for (int b = a + 1 + lane; b < cnt; b += 32) {
                    const float4* rb = (const float4*)(rows + b * ROWSTRIDE);
                    float dot = 0.f;
#pragma unroll 8
                    for (int k = 0; k < H / 4; k++) {
                        float4 u = ra[k], v = rb[k];
                        dot = fmaf(u.x, v.x, dot);
                        dot = fmaf(u.y, v.y, dot);
                        dot = fmaf(u.z, v.z, dot);
                        dot = fmaf(u.w, v.w, dot);
                    }
                    float e = dot - C_SIM;
                    acc = fmaf(e, e, acc);
                }
            }
            if (feat == 0) sacc = acc; else dacc += acc;
            __syncthreads();
        }
    } else if (cnt > MAXM) {
        for (int feat = 0; feat < 4; feat++) {
            float acc = 0.f;
            for (int a = w; a < cnt - 1; a += 8) {
                int na = g_nodes[off + a];
                const float* ra; float inva;
                if (feat == 0) { ra = g_si + (size_t)na * H; inva = g_inv_s[na]; }
                else { ra = g_vi + ((size_t)na * 3 + (feat - 1)) * H; inva = g_inv_v[na * 3 + feat - 1]; }
                for (int b = a + 1 + lane; b < cnt; b += 32) {
                    int nb = g_nodes[off + b];
                    const float* rb; float invb;
                    if (feat == 0) { rb = g_si + (size_t)nb * H; invb = g_inv_s[nb]; }
                    else { rb = g_vi + ((size_t)nb * 3 + (feat - 1)) * H; invb = g_inv_v[nb * 3 + feat - 1]; }
                    float dot = 0.f;
                    for (int k = 0; k < H; k++) dot = fmaf(ra[k], rb[k], dot);
                    float e = dot * inva * invb - C_SIM;
                    acc = fmaf(e, e, acc);
                }
            }
            if (feat == 0) sacc = acc; else dacc += acc;
        }
    }

    __shared__ float red[64];
    for (int o = 16; o; o >>= 1) {
        sacc += __shfl_xor_sync(0xffffffffu, sacc, o);
        dacc += __shfl_xor_sync(0xffffffffu, dacc, o);
    }
    if (lane == 0) { red[w] = sacc; red[32 + w] = dacc; }
    __syncthreads();
    if (t == 0) {
        float a = 0.f, b = 0.f;
        for (int i = 0; i < 8; i++) { a += red[i]; b += red[32 + i]; }
        g_ssim[f] = a; g_dir[f] = b;
    }
}

// ---------------- final scalar ----------------
__global__ void k_final(float* __restrict__ out) {
    int f = threadIdx.x;
    float n  = (float)g_counts[f];
    float pc = n * (n - 1.f) * 0.5f;
    float ns  = fmaxf(n, 1.f);
    float pcs = fmaxf(pc, 1.f);
    float sl = g_svar[f] / ns + g_ssim[f] / pcs;
    float vl = g_vvar[f] / ns + g_dir[f] / (3.f * pcs);
    float fl = 0.5f * sl + 0.5f * vl;
    float val  = (pc > 0.f) ? fl : 0.f;
    float cntv = (pc > 0.f) ? 1.f : 0.f;
    __shared__ float red[64];
    for (int o = 16; o; o >>= 1) {
        val  += __shfl_xor_sync(0xffffffffu, val, o);
        cntv += __shfl_xor_sync(0xffffffffu, cntv, o);
    }
    int w = f >> 5, lane = f & 31;
    if (lane == 0) { red[w] = val; red[32 + w] = cntv; }
    __syncthreads();
    if (f == 0) {
        float tot = 0.f, tc = 0.f;
        for (int i = 0; i < 8; i++) { tot += red[i]; tc += red[32 + i]; }
        out[0] = (tc > 0.f) ? tot / fmaxf(tc, 1.f) : 0.f;
    }
}

// ---------------- launch ----------------
extern "C" void kernel_launch(void* const* d_in, const int* in_sizes, int n_in,
                              void* d_out, int out_size)
{
    const float* ss = (const float*)d_in[0];
    const float* sl = (const float*)d_in[1];
    const float* vs = (const float*)d_in[2];
    const float* vl = (const float*)d_in[3];
    const float* W1 = (const float*)d_in[4];
    const float* b1 = (const float*)d_in[5];
    const float* W2 = (const float*)d_in[6];
    const float* b2 = (const float*)d_in[7];
    const float* V1 = (const float*)d_in[8];
    const float* V2 = (const float*)d_in[9];
    const int*   frag = (const int*)d_in[10];
    float* out = (float*)d_out;

    void *pt, *psi, *pvi, *pch;
    cudaGetSymbolAddress(&pt,  g_t);
    cudaGetSymbolAddress(&psi, g_si);
    cudaGetSymbolAddress(&pvi, g_vi);
    cudaGetSymbolAddress(&pch, g_chunk);

    cudaMemsetAsync(pch, 0, 256 * 256 * sizeof(int));
    k_hist<<<32, 256>>>(frag);
    k_scan2<<<1, 256>>>();
    k_scatter<<<32, 256>>>(frag);

    dim3 gsc(2, 64);    // M=8192  / 128
    dim3 gvc(2, 192);   // M=24576 / 128
    k_gemm<<<gsc, 256>>>(ss, sl, W1, b1, (float*)pt, 1);
    k_gemm<<<gsc, 256>>>((float*)pt, nullptr, W2, b2, (float*)psi, 0);
    k_gemm<<<gvc, 256>>>(vs, vl, V1, nullptr, (float*)pt, 1);
    k_gemm<<<gvc, 256>>>((float*)pt, nullptr, V2, nullptr, (float*)pvi, 0);

    k_norms<<<N_NODES * 32 / 256, 256>>>();
    k_meanvar<<<NF, 256>>>();

    cudaFuncSetAttribute(k_pairs, cudaFuncAttributeMaxDynamicSharedMemorySize,
                         MAXM * ROWSTRIDE * 4);
    k_pairs<<<NF, 256, MAXM * ROWSTRIDE * 4>>>();

    k_final<<<1, 256>>>(out);
}

// round 6
// speedup vs baseline: 1.9871x; 1.1438x over previous
#include <cuda_runtime.h>
#include <cuda_bf16.h>
#include <math.h>
#include <stdint.h>

#define N_NODES 8192
#define H 256
#define NF 256
#define R_MIX 0.3f
#define C_SIM 0.8f
#define LOG2F_ 0.69314718055994530942f
#define MAXM 128
#define ROWSTRIDE 260

// ---------------- scratch (static device globals) ----------------
__device__ float g_ts[ 8192 * 256];   // scalar layer-1 output
__device__ float g_tv[24576 * 256];   // vector layer-1 output
__device__ float g_si[ 8192 * 256];   // scalar branch output [N,H]
__device__ float g_vi[24576 * 256];   // vector branch output [N,3,H]
__device__ int   g_chunk[256 * 256];
__device__ int   g_counts [NF];
__device__ int   g_offsets[NF + 1];
__device__ int   g_nodes  [N_NODES];
__device__ float g_svar[NF], g_vvar[NF], g_ssim[NF], g_dir[NF];
__device__ float g_inv_s[N_NODES];
__device__ float g_inv_v[N_NODES * 3];

__device__ __forceinline__ float sspf(float x) {
    float ax = fabsf(x);
    return fmaxf(x, 0.f) + log1pf(__expf(-ax)) - LOG2F_;
}
__device__ __forceinline__ uint32_t pk2(float a, float b) {
    __nv_bfloat162 t = __floats2bfloat162_rn(a, b);
    return *reinterpret_cast<uint32_t*>(&t);
}
__device__ __forceinline__ float bres(float x) {
    __nv_bfloat16 h = __float2bfloat16(x);
    return x - __bfloat162float(h);
}

// ---------------- mma/ldmatrix wrappers (sm_103-safe: no tcgen05) ----------------
__device__ __forceinline__ void ldsm4(uint32_t addr, uint32_t* r) {
    asm volatile("ldmatrix.sync.aligned.m8n8.x4.shared.b16 {%0,%1,%2,%3}, [%4];"
                 : "=r"(r[0]), "=r"(r[1]), "=r"(r[2]), "=r"(r[3]) : "r"(addr));
}
__device__ __forceinline__ void ldsm4t(uint32_t addr, uint32_t* r) {
    asm volatile("ldmatrix.sync.aligned.m8n8.x4.trans.shared.b16 {%0,%1,%2,%3}, [%4];"
                 : "=r"(r[0]), "=r"(r[1]), "=r"(r[2]), "=r"(r[3]) : "r"(addr));
}
__device__ __forceinline__ void mma16816(float* c, const uint32_t* a, uint32_t b0, uint32_t b1) {
    asm volatile(
        "mma.sync.aligned.m16n8k16.row.col.f32.bf16.bf16.f32 "
        "{%0,%1,%2,%3},{%4,%5,%6,%7},{%8,%9},{%0,%1,%2,%3};"
        : "+f"(c[0]), "+f"(c[1]), "+f"(c[2]), "+f"(c[3])
        : "r"(a[0]), "r"(a[1]), "r"(a[2]), "r"(a[3]), "r"(b0), "r"(b1));
}

// ---------------- fragment bookkeeping (deterministic counting sort) -----------
__global__ void k_hist(const int* __restrict__ frag) {
    int chunk = blockIdx.x * 8 + (threadIdx.x >> 5);
    int lane = threadIdx.x & 31;
    int i = chunk * 32 + lane;
    int f = frag[i];
    unsigned mask = __match_any_sync(0xffffffffu, f);
    int lr = __popc(mask & ((1u << lane) - 1u));
    if (lr == 0 && f >= 0 && f < NF) g_chunk[chunk * 256 + f] = __popc(mask);
}

__global__ void k_scan2() {
    int t = threadIdx.x;
    int running = 0;
    for (int c = 0; c < 256; c++) {
        int idx = c * 256 + t;
        int v = g_chunk[idx];
        g_chunk[idx] = running;
        running += v;
    }
    g_counts[t] = running;
    __shared__ int s[256];
    s[t] = running;
    __syncthreads();
    for (int d = 1; d < 256; d <<= 1) {
        int v = (t >= d) ? s[t - d] : 0;
        __syncthreads();
        s[t] += v;
        __syncthreads();
    }
    g_offsets[t] = s[t] - running;
    if (t == 255) g_offsets[256] = s[255];
}

__global__ void k_scatter(const int* __restrict__ frag) {
    int chunk = blockIdx.x * 8 + (threadIdx.x >> 5);
    int lane = threadIdx.x & 31;
    int i = chunk * 32 + lane;
    int f = frag[i];
    unsigned mask = __match_any_sync(0xffffffffu, f);
    int lr = __popc(mask & ((1u << lane) - 1u));
    if (f >= 0 && f < NF) {
        int pos = g_offsets[f] + g_chunk[chunk * 256 + f] + lr;
        if (pos >= 0 && pos < N_NODES) g_nodes[pos] = i;
    }
}

// ------------- merged tensor-core GEMM (scalar + vector branch in ONE grid) -----
// grid = (2, nScalar + nVector). blockIdx.y < nScalar -> scalar branch pointers.
// bf16 3-term split (AhBh + AlBh + AhBl), CTA tile 128x128, 8 warps of 64x32,
// double-buffered smem, one __syncthreads per 16-k chunk.

#define AROW 24
#define BROW 136
#define A_HL (128 * AROW)
#define B_HL (16 * BROW)
#define NSCALAR_BLOCKS 64

__device__ __forceinline__ void gloadA(const float* __restrict__ a1p,
                                       const float* __restrict__ a2p,
                                       int k0, float4& x, float4& y) {
    x = *(const float4*)(a1p + k0);
    y = *(const float4*)(a1p + k0 + 4);
    if (a2p) {
        float4 u = *(const float4*)(a2p + k0);
        float4 v = *(const float4*)(a2p + k0 + 4);
        const float w = 1.f - R_MIX;
        x.x = fmaf(x.x, R_MIX, u.x * w); x.y = fmaf(x.y, R_MIX, u.y * w);
        x.z = fmaf(x.z, R_MIX, u.z * w); x.w = fmaf(x.w, R_MIX, u.w * w);
        y.x = fmaf(y.x, R_MIX, v.x * w); y.y = fmaf(y.y, R_MIX, v.y * w);
        y.z = fmaf(y.z, R_MIX, v.z * w); y.w = fmaf(y.w, R_MIX, v.w * w);
    }
}

__device__ __forceinline__ void cvt_store8(uint16_t* hi_p, uint16_t* lo_p,
                                           const float4& x, const float4& y) {
    uint4 hv, lv;
    hv.x = pk2(x.x, x.y); hv.y = pk2(x.z, x.w);
    hv.z = pk2(y.x, y.y); hv.w = pk2(y.z, y.w);
    lv.x = pk2(bres(x.x), bres(x.y)); lv.y = pk2(bres(x.z), bres(x.w));
    lv.z = pk2(bres(y.x), bres(y.y)); lv.w = pk2(bres(y.z), bres(y.w));
    *reinterpret_cast<uint4*>(hi_p) = hv;
    *reinterpret_cast<uint4*>(lo_p) = lv;
}

__global__ __launch_bounds__(256, 2)
void k_gemm(const float* __restrict__ A1s, const float* __restrict__ A2s,
            const float* __restrict__ A1v, const float* __restrict__ A2v,
            const float* __restrict__ Bs,  const float* __restrict__ biass,
            const float* __restrict__ Bv,  const float* __restrict__ biasv,
            float* __restrict__ Cs, float* __restrict__ Cv, int useSSP)
{
    __shared__ __align__(16) uint16_t sA[2][2][A_HL];
    __shared__ __align__(16) uint16_t sB[2][2][B_HL];

    const int tid = threadIdx.x;
    const int lane = tid & 31;
    const int wid = tid >> 5;
    const int warp_m = wid >> 2;
    const int warp_n = wid & 3;

    // branch selection
    const bool isS = (blockIdx.y < NSCALAR_BLOCKS);
    const size_t rowBase = (size_t)(isS ? blockIdx.y : blockIdx.y - NSCALAR_BLOCKS) * 128;
    const int colBase = blockIdx.x * 128;
    const float* A1 = isS ? A1s : A1v;
    const float* A2 = isS ? A2s : A2v;
    const float* B  = isS ? Bs  : Bv;
    const float* bias = isS ? biass : biasv;
    float* Cc = isS ? Cs : Cv;

    const int am = tid >> 1;
    const int ak = (tid & 1) * 8;
    const int bk = tid >> 4;
    const int bn = (tid & 15) * 8;

    const float* a1p = A1 + (rowBase + am) * H + ak;
    const float* a2p = A2 ? A2 + (rowBase + am) * H + ak : nullptr;
    const float* bp  = B + (size_t)bk * H + colBase + bn;

    const int a_row0 = warp_m * 64 + (lane & 7) + ((lane >> 3) & 1) * 8;
    const int a_kgrp = lane >> 4;
    uint32_t aBase = (uint32_t)__cvta_generic_to_shared(&sA[0][0][0])
                   + (uint32_t)((a_row0 * AROW + a_kgrp * 8) * 2);
    const int b_krow = (lane & 7) + ((lane >> 3) & 1) * 8;
    const int b_ngrp = lane >> 4;
    uint32_t bBase = (uint32_t)__cvta_generic_to_shared(&sB[0][0][0])
                   + (uint32_t)((b_krow * BROW + warp_n * 32 + b_ngrp * 8) * 2);

    float acc[4][4][4];
#pragma unroll
    for (int i = 0; i < 4; i++)
#pragma unroll
        for (int j = 0; j < 4; j++)
#pragma unroll
            for (int q = 0; q < 4; q++) acc[i][j][q] = 0.f;

    float4 ax, ay, bx, by;
    gloadA(a1p, a2p, 0, ax, ay);
    bx = *(const float4*)(bp);
    by = *(const float4*)(bp + 4);
    cvt_store8(&sA[0][0][am * AROW + ak], &sA[0][1][am * AROW + ak], ax, ay);
    cvt_store8(&sB[0][0][bk * BROW + bn], &sB[0][1][bk * BROW + bn], bx, by);
    __syncthreads();

    const int NT = H / 16;
    for (int t = 0; t < NT; t++) {
        if (t + 1 < NT) {
            int k0 = (t + 1) * 16;
            gloadA(a1p, a2p, k0, ax, ay);
            bx = *(const float4*)(bp + (size_t)k0 * H);
            by = *(const float4*)(bp + (size_t)k0 * H + 4);
        }
        int buf = t & 1;
        uint32_t aOff = aBase + (uint32_t)(buf * 2 * A_HL * 2);
        uint32_t bOff = bBase + (uint32_t)(buf * 2 * B_HL * 2);

        uint32_t ah[4][4], bh[2][4], tmp[2][4], al4[4];
#pragma unroll
        for (int mt = 0; mt < 4; mt++) ldsm4(aOff + mt * (16 * AROW * 2), ah[mt]);
#pragma unroll
        for (int st = 0; st < 2; st++) ldsm4t(bOff + st * 32, bh[st]);
#pragma unroll
        for (int mt = 0; mt < 4; mt++)
#pragma unroll
            for (int nt = 0; nt < 4; nt++)
                mma16816(acc[mt][nt], ah[mt], bh[nt >> 1][(nt & 1) * 2],
                         bh[nt >> 1][(nt & 1) * 2 + 1]);
#pragma unroll
        for (int st = 0; st < 2; st++) ldsm4t(bOff + B_HL * 2 + st * 32, tmp[st]);
#pragma unroll
        for (int mt = 0; mt < 4; mt++)
#pragma unroll
            for (int nt = 0; nt < 4; nt++)
                mma16816(acc[mt][nt], ah[mt], tmp[nt >> 1][(nt & 1) * 2],
                         tmp[nt >> 1][(nt & 1) * 2 + 1]);
#pragma unroll
        for (int mt = 0; mt < 4; mt++) {
            ldsm4(aOff + A_HL * 2 + mt * (16 * AROW * 2), al4);
#pragma unroll
            for (int nt = 0; nt < 4; nt++)
                mma16816(acc[mt][nt], al4, bh[nt >> 1][(nt & 1) * 2],
                         bh[nt >> 1][(nt & 1) * 2 + 1]);
        }

        if (t + 1 < NT) {
            int nb = (t + 1) & 1;
            cvt_store8(&sA[nb][0][am * AROW + ak], &sA[nb][1][am * AROW + ak], ax, ay);
            cvt_store8(&sB[nb][0][bk * BROW + bn], &sB[nb][1][bk * BROW + bn], bx, by);
        }
        __syncthreads();
    }

#pragma unroll
    for (int mt = 0; mt < 4; mt++) {
        size_t r0 = rowBase + warp_m * 64 + mt * 16 + (lane >> 2);
#pragma unroll
        for (int nt = 0; nt < 4; nt++) {
            int col = colBase + warp_n * 32 + nt * 8 + (lane & 3) * 2;
            float v0 = acc[mt][nt][0], v1 = acc[mt][nt][1];
            float v2 = acc[mt][nt][2], v3 = acc[mt][nt][3];
            if (bias) {
                float2 bb = *(const float2*)&bias[col];
                v0 += bb.x; v1 += bb.y; v2 += bb.x; v3 += bb.y;
            }
            if (useSSP) { v0 = sspf(v0); v1 = sspf(v1); v2 = sspf(v2); v3 = sspf(v3); }
            float2 o0; o0.x = v0; o0.y = v1;
            float2 o1; o1.x = v2; o1.y = v3;
            *(float2*)&Cc[r0 * H + col] = o0;
            *(float2*)&Cc[(r0 + 8) * H + col] = o1;
        }
    }
}

// ---------------- per-node inverse L2 norms (warp per node) ----------------
__global__ void k_norms() {
    int gw = (blockIdx.x * blockDim.x + threadIdx.x) >> 5;
    int lane = threadIdx.x & 31;
    if (gw >= N_NODES) return;
    const float* p = g_si + (size_t)gw * H;
    float s = 0.f;
    for (int j = lane; j < H; j += 32) { float v = p[j]; s = fmaf(v, v, s); }
    for (int o = 16; o; o >>= 1) s += __shfl_xor_sync(0xffffffffu, s, o);
    if (lane == 0) g_inv_s[gw] = 1.f / fmaxf(sqrtf(s), 1e-12f);
#pragma unroll
    for (int d = 0; d < 3; d++) {
        const float* q = g_vi + ((size_t)gw * 3 + d) * H;
        float t = 0.f;
        for (int j = lane; j < H; j += 32) { float v = q[j]; t = fmaf(v, v, t); }
        for (int o = 16; o; o >>= 1) t += __shfl_xor_sync(0xffffffffu, t, o);
        if (lane == 0) g_inv_v[gw * 3 + d] = 1.f / fmaxf(sqrtf(t), 1e-12f);
    }
}

// ---------------- per-fragment mean + variance ----------------
__global__ void k_meanvar() {
    __shared__ float mean[1024];
    int f = blockIdx.x, t = threadIdx.x;
    int cnt = g_counts[f], off = g_offsets[f];
    float as = 0.f, a0 = 0.f, a1 = 0.f, a2 = 0.f;
    for (int m = 0; m < cnt; m++) {
        int nd = g_nodes[off + m];
        as += g_si[(size_t)nd * H + t];
        const float* v = g_vi + (size_t)nd * 3 * H;
        a0 += v[t]; a1 += v[H + t]; a2 += v[2 * H + t];
    }
    float invn = 1.f / (float)(cnt > 1 ? cnt : 1);
    mean[t] = as * invn; mean[256 + t] = a0 * invn;
    mean[512 + t] = a1 * invn; mean[768 + t] = a2 * invn;
    __syncthreads();
    float sv = 0.f, vv = 0.f;
    for (int m = 0; m < cnt; m++) {
        int nd = g_nodes[off + m];
        float d0 = g_si[(size_t)nd * H + t] - mean[t];
        sv = fmaf(d0, d0, sv);
        const float* v = g_vi + (size_t)nd * 3 * H;
        float d1 = v[t] - mean[256 + t];
        float d2 = v[H + t] - mean[512 + t];
        float d3 = v[2 * H + t] - mean[768 + t];
        vv = fmaf(d1, d1, vv); vv = fmaf(d2, d2, vv); vv = fmaf(d3, d3, vv);
    }
    __shared__ float red[64];
    for (int o = 16; o; o >>= 1) {
        sv += __shfl_xor_sync(0xffffffffu, sv, o);
        vv += __shfl_xor_sync(0xffffffffu, vv, o);
    }
    int w = t >> 5, lane = t & 31;
    if (lane == 0) { red[w] = sv; red[32 + w] = vv; }
    __syncthreads();
    if (t == 0) {
        float a = 0.f, b = 0.f;
        for (int i = 0; i < 8; i++) { a += red[i]; b += red[32 + i]; }
        g_svar[f] = a; g_vvar[f] = b;
    }
}

// ---------------- intra-fragment pair cosine error ----------------
__global__ void k_pairs() {
    extern __shared__ float rows[];
    int f = blockIdx.x, t = threadIdx.x;
    int cnt = g_counts[f], off = g_offsets[f];
    int w = t >> 5, lane = t & 31;
    float sacc = 0.f, dacc = 0.f;

    if (cnt >= 2 && cnt <= MAXM) {
        for (int feat = 0; feat < 4; feat++) {
            for (int r = 0; r < cnt; r++) {
                int nd = g_nodes[off + r];
                const float* src; float inv;
                if (feat == 0) { src = g_si + (size_t)nd * H; inv = g_inv_s[nd]; }
                else { src = g_vi + ((size_t)nd * 3 + (feat - 1)) * H; inv = g_inv_v[nd * 3 + feat - 1]; }
                rows[r * ROWSTRIDE + t] = src[t] * inv;
            }
            __syncthreads();
            float acc = 0.f;
            for (int a = w; a < cnt - 1; a += 8) {
                const float4* ra = (const float4*)(rows + a * ROWSTRIDE);
                for (int b = a + 1 + lane; b < cnt; b += 32) {
                    const float4* rb = (const float4*)(rows + b * ROWSTRIDE);
                    float dot = 0.f;
#pragma unroll 8
                    for (int k = 0; k < H / 4; k++) {
                        float4 u = ra[k], v = rb[k];
                        dot = fmaf(u.x, v.x, dot);
                        dot = fmaf(u.y, v.y, dot);
                        dot = fmaf(u.z, v.z, dot);
                        dot = fmaf(u.w, v.w, dot);
                    }
                    float e = dot - C_SIM;
                    acc = fmaf(e, e, acc);
                }
            }
            if (feat == 0) sacc = acc; else dacc += acc;
            __syncthreads();
        }
    } else if (cnt > MAXM) {
        for (int feat = 0; feat < 4; feat++) {
            float acc = 0.f;
            for (int a = w; a < cnt - 1; a += 8) {
                int na = g_nodes[off + a];
                const float* ra; float inva;
                if (feat == 0) { ra = g_si + (size_t)na * H; inva = g_inv_s[na]; }
                else { ra = g_vi + ((size_t)na * 3 + (feat - 1)) * H; inva = g_inv_v[na * 3 + feat - 1]; }
                for (int b = a + 1 + lane; b < cnt; b += 32) {
                    int nb = g_nodes[off + b];
                    const float* rb; float invb;
                    if (feat == 0) { rb = g_si + (size_t)nb * H; invb = g_inv_s[nb]; }
                    else { rb = g_vi + ((size_t)nb * 3 + (feat - 1)) * H; invb = g_inv_v[nb * 3 + feat - 1]; }
                    float dot = 0.f;
                    for (int k = 0; k < H; k++) dot = fmaf(ra[k], rb[k], dot);
                    float e = dot * inva * invb - C_SIM;
                    acc = fmaf(e, e, acc);
                }
            }
            if (feat == 0) sacc = acc; else dacc += acc;
        }
    }

    __shared__ float red[64];
    for (int o = 16; o; o >>= 1) {
        sacc += __shfl_xor_sync(0xffffffffu, sacc, o);
        dacc += __shfl_xor_sync(0xffffffffu, dacc, o);
    }
    if (lane == 0) { red[w] = sacc; red[32 + w] = dacc; }
    __syncthreads();
    if (t == 0) {
        float a = 0.f, b = 0.f;
        for (int i = 0; i < 8; i++) { a += red[i]; b += red[32 + i]; }
        g_ssim[f] = a; g_dir[f] = b;
    }
}

// ---------------- final scalar ----------------
__global__ void k_final(float* __restrict__ out) {
    int f = threadIdx.x;
    float n  = (float)g_counts[f];
    float pc = n * (n - 1.f) * 0.5f;
    float ns  = fmaxf(n, 1.f);
    float pcs = fmaxf(pc, 1.f);
    float sl = g_svar[f] / ns + g_ssim[f] / pcs;
    float vl = g_vvar[f] / ns + g_dir[f] / (3.f * pcs);
    float fl = 0.5f * sl + 0.5f * vl;
    float val  = (pc > 0.f) ? fl : 0.f;
    float cntv = (pc > 0.f) ? 1.f : 0.f;
    __shared__ float red[64];
    for (int o = 16; o; o >>= 1) {
        val  += __shfl_xor_sync(0xffffffffu, val, o);
        cntv += __shfl_xor_sync(0xffffffffu, cntv, o);
    }
    int w = f >> 5, lane = f & 31;
    if (lane == 0) { red[w] = val; red[32 + w] = cntv; }
    __syncthreads();
    if (f == 0) {
        float tot = 0.f, tc = 0.f;
        for (int i = 0; i < 8; i++) { tot += red[i]; tc += red[32 + i]; }
        out[0] = (tc > 0.f) ? tot / fmaxf(tc, 1.f) : 0.f;
    }
}

// ---------------- launch ----------------
extern "C" void kernel_launch(void* const* d_in, const int* in_sizes, int n_in,
                              void* d_out, int out_size)
{
    const float* ss = (const float*)d_in[0];
    const float* sl = (const float*)d_in[1];
    const float* vs = (const float*)d_in[2];
    const float* vl = (const float*)d_in[3];
    const float* W1 = (const float*)d_in[4];
    const float* b1 = (const float*)d_in[5];
    const float* W2 = (const float*)d_in[6];
    const float* b2 = (const float*)d_in[7];
    const float* V1 = (const float*)d_in[8];
    const float* V2 = (const float*)d_in[9];
    const int*   frag = (const int*)d_in[10];
    float* out = (float*)d_out;

    void *pts, *ptv, *psi, *pvi, *pch;
    cudaGetSymbolAddress(&pts, g_ts);
    cudaGetSymbolAddress(&ptv, g_tv);
    cudaGetSymbolAddress(&psi, g_si);
    cudaGetSymbolAddress(&pvi, g_vi);
    cudaGetSymbolAddress(&pch, g_chunk);
    float* ts = (float*)pts;
    float* tv = (float*)ptv;
    float* si = (float*)psi;
    float* vi = (float*)pvi;

    cudaMemsetAsync(pch, 0, 256 * 256 * sizeof(int));
    k_hist<<<32, 256>>>(frag);
    k_scan2<<<1, 256>>>();
    k_scatter<<<32, 256>>>(frag);

    // merged-branch GEMMs: grid y = 64 scalar blocks + 192 vector blocks
    dim3 g(2, NSCALAR_BLOCKS + 192);
    // layer 1: ts = ssp(mix(ss,sl)@W1 + b1), tv = ssp(mix(vs,vl)@V1)
    k_gemm<<<g, 256>>>(ss, sl, vs, vl, W1, b1, V1, nullptr, ts, tv, 1);
    // layer 2: si = ts@W2 + b2, vi = tv@V2
    k_gemm<<<g, 256>>>(ts, nullptr, tv, nullptr, W2, b2, V2, nullptr, si, vi, 0);

    k_norms<<<N_NODES * 32 / 256, 256>>>();
    k_meanvar<<<NF, 256>>>();

    cudaFuncSetAttribute(k_pairs, cudaFuncAttributeMaxDynamicSharedMemorySize,
                         MAXM * ROWSTRIDE * 4);
    k_pairs<<<NF, 256, MAXM * ROWSTRIDE * 4>>>();

    k_final<<<1, 256>>>(out);
}